// round 8
// baseline (speedup 1.0000x reference)
#include <cuda_runtime.h>

#define BB 2048
#define CC 9605
#define TOT4 4917760          // BB*CC/4 (exact)
#define NT 256
#define GA 2368               // phase-A grid (16 per SM)
#define GB 256                // phase-B grid: 8 warps/block, 1 warp per row
#define CAPG 512
#define XTHRESH 2.0f
#define EPSF 1e-8f

__device__ float              g_partA[GA];
__device__ float              g_partB[GB];
__device__ int                g_cnt[BB];            // zero-init; reset each run by phase B
__device__ unsigned long long g_cand[BB * CAPG];
__device__ int                g_done = 0;

// base * w for one element; y is exactly 0.0f or 1.0f so FFMA blends replace selects
__device__ __forceinline__ float term_bw(float xv, float yv) {
    float p  = __fdividef(1.0f, 1.0f + __expf(-xv));   // sigmoid
    float xn = fminf(1.05f - p, 1.0f);                 // xs_neg
    float o  = fmaxf(p - 0.05f, 0.0f);                 // 1 - xs_neg
    float o2 = o * o;
    float o4 = o2 * o2;                                // (1-pt)^4 (neg)
    float arg = fmaf(yv, fmaxf(p, EPSF) - xn, xn);     // pos ? max(p,eps) : xn
    float w   = fmaf(yv, (1.0f - p) - o4, o4);         // pos ? (1-p) : o4
    return __logf(arg) * w;
}

// monotone float->uint mapping so u64 key max == (max val, then min idx)
__device__ __forceinline__ unsigned long long pack_key(float v, int idx) {
    unsigned u = __float_as_uint(v);
    u = (u & 0x80000000u) ? ~u : (u | 0x80000000u);
    return ((unsigned long long)u << 32) | (unsigned)(0xFFFFFFFFu - (unsigned)idx);
}

__device__ __forceinline__ void maybe_push(float v, int c) {
    if (v > XTHRESH) {
        int row = c / CC;            // rare path (~2.3% of elements)
        int cid = c - row * CC;
        int k = atomicAdd(&g_cnt[row], 1);
        if (k < CAPG) g_cand[row * CAPG + k] = pack_key(v, cid);
    }
}

__device__ __forceinline__ float proc4(const float4& xv, const float4& yv, int c0) {
    float t = term_bw(xv.x, yv.x) + term_bw(xv.y, yv.y)
            + term_bw(xv.z, yv.z) + term_bw(xv.w, yv.w);
    float mx = fmaxf(fmaxf(xv.x, xv.y), fmaxf(xv.z, xv.w));
    if (mx > XTHRESH) {
        maybe_push(xv.x, c0);     maybe_push(xv.y, c0 + 1);
        maybe_push(xv.z, c0 + 2); maybe_push(xv.w, c0 + 3);
    }
    return t;
}

// ── Phase A: flat bandwidth stream, no row structure in the hot path ──
__global__ __launch_bounds__(NT)
void streamA(const float4* __restrict__ x4, const float4* __restrict__ y4)
{
    const int tid = threadIdx.x;
    const int stride = GA * NT;
    float acc = 0.0f;

    int i = blockIdx.x * NT + tid;
    // unrolled-by-2 grid-stride: 4 independent LDG.128 front-batched per step
    for (; i + stride < TOT4; i += 2 * stride) {
        float4 xa = __ldcs(x4 + i);
        float4 ya = __ldcs(y4 + i);
        float4 xb = __ldcs(x4 + i + stride);
        float4 yb = __ldcs(y4 + i + stride);
        acc += proc4(xa, ya, 4 * i);
        acc += proc4(xb, yb, 4 * (i + stride));
    }
    if (i < TOT4) {
        float4 xa = __ldcs(x4 + i);
        float4 ya = __ldcs(y4 + i);
        acc += proc4(xa, ya, 4 * i);
    }

    // block reduce
    __shared__ float s[NT / 32];
    const int lane = tid & 31, wid = tid >> 5;
    #pragma unroll
    for (int o = 16; o > 0; o >>= 1) acc += __shfl_xor_sync(0xFFFFFFFFu, acc, o);
    if (lane == 0) s[wid] = acc;
    __syncthreads();
    if (wid == 0) {
        float a = (lane < NT / 32) ? s[lane] : 0.0f;
        #pragma unroll
        for (int o = 16; o > 0; o >>= 1) a += __shfl_xor_sync(0xFFFFFFFFu, a, o);
        if (lane == 0) g_partA[blockIdx.x] = a;
    }
}

// ── Phase B: one warp per row — flags, top-10, correction, final reduce ──
__global__ __launch_bounds__(NT)
void phaseB(const float* __restrict__ x, const float* __restrict__ y,
            const int* __restrict__ ci, const int* __restrict__ ri,
            const int* __restrict__ di, const int* __restrict__ wl,
            float* __restrict__ out)
{
    const int tid  = threadIdx.x;
    const int lane = tid & 31;
    const int wid  = tid >> 5;
    const int row  = blockIdx.x * (NT / 32) + wid;

    const float* __restrict__ xr = x + (size_t)row * CC;
    const float* __restrict__ yr = y + (size_t)row * CC;

    // group flags via sparse y lookups
    unsigned f = 0;
    if (lane < 30 && yr[ci[lane]] > 0.5f) f |= 1;
    for (int q = lane; q < 70; q += 32) {
        if (yr[ri[q]] > 0.5f) f |= 2;
        if (yr[di[q]] > 0.5f) f |= 4;
    }
    f = __reduce_or_sync(0xFFFFFFFFu, f);

    const int cnt = g_cnt[row];
    const int nk  = (cnt < CAPG) ? cnt : CAPG;
    const bool fb = (cnt < 10) || (cnt > CAPG);

    // candidates into registers (16 * 32 = CAPG slots)
    unsigned long long kc[CAPG / 32];
    #pragma unroll
    for (int t = 0; t < CAPG / 32; t++) {
        int k = lane + t * 32;
        kc[t] = (!fb && k < nk) ? g_cand[row * CAPG + k] : 0ull;
    }

    int sel[10];
    if (!fb) {
        #pragma unroll
        for (int r = 0; r < 10; r++) {
            unsigned long long best = 0ull;
            #pragma unroll
            for (int t = 0; t < CAPG / 32; t++) if (kc[t] > best) best = kc[t];
            #pragma unroll
            for (int o = 16; o > 0; o >>= 1) {
                unsigned long long tt = __shfl_xor_sync(0xFFFFFFFFu, best, o);
                if (tt > best) best = tt;
            }
            sel[r] = (int)(0xFFFFFFFFu - (unsigned)best);
            #pragma unroll
            for (int t = 0; t < CAPG / 32; t++) if (kc[t] == best) kc[t] = 0ull;
        }
    } else {
        // guaranteed-correct fallback: 10 argmax passes over the full row
        for (int r = 0; r < 10; r++) {
            unsigned long long best = 0ull;
            for (int c = lane; c < CC; c += 32) {
                bool used = false;
                for (int q = 0; q < r; q++) used |= (sel[q] == c);
                if (!used) {
                    unsigned long long key = pack_key(xr[c], c);
                    if (key > best) best = key;
                }
            }
            #pragma unroll
            for (int o = 16; o > 0; o >>= 1) {
                unsigned long long tt = __shfl_xor_sync(0xFFFFFFFFu, best, o);
                if (tt > best) best = tt;
            }
            sel[r] = (int)(0xFFFFFFFFu - (unsigned)best);
        }
    }

    // sequential 10-rank whitelist scan + correction (lane 0)
    float corr = 0.0f;
    if (lane == 0) {
        bool h1 = f & 1, h2 = f & 2, h3 = f & 4;
        bool only4 = !(h1 || h2 || h3);
        bool found = false;
        float fm[10];
        #pragma unroll
        for (int r = 0; r < 10; r++) {
            int j = sel[r];
            int wv = wl[j];
            bool in_map = wv > 0;
            bool in_gt = (wv == 1 && h1) || (wv == 2 && h2) ||
                         (wv == 3 && h3) || (wv == 4 && only4);
            float ff = 1.0f;
            if (in_map && only4) ff *= 0.5f;                 // ALPHA_OTHER
            if (in_map && !in_gt && !found) ff *= 2.0f;      // ALPHA1
            fm[r] = ff;
            found = found || (in_map && in_gt);
        }
        float extra = found ? 1.0f : 2.0f;                   // post-scan ALPHA1
        #pragma unroll
        for (int r = 0; r < 10; r++) {
            float m = fm[r] * extra;
            if (m != 1.0f) {
                int j = sel[r];
                corr += term_bw(xr[j], yr[j]) * (m - 1.0f);
            }
        }
        g_cnt[row] = 0;          // reset for next graph replay
    }

    // block reduce of 8 per-warp corrections
    __shared__ float s_c[NT / 32];
    if (lane == 0) s_c[wid] = corr;
    __syncthreads();
    if (wid != 0) return;
    float bsum = (lane < NT / 32) ? s_c[lane] : 0.0f;
    #pragma unroll
    for (int o = 16; o > 0; o >>= 1) bsum += __shfl_xor_sync(0xFFFFFFFFu, bsum, o);
    if (lane == 0) g_partB[blockIdx.x] = bsum;

    // last block performs the deterministic fixed-order final reduction
    int done = 0;
    if (lane == 0) {
        __threadfence();
        done = atomicAdd(&g_done, 1);
    }
    done = __shfl_sync(0xFFFFFFFFu, done, 0);
    if (done == GB - 1) {
        __threadfence();
        float a = 0.0f;
        for (int k = lane; k < GA; k += 32) a += g_partA[k];
        for (int k = lane; k < GB; k += 32) a += g_partB[k];
        #pragma unroll
        for (int o = 16; o > 0; o >>= 1) a += __shfl_xor_sync(0xFFFFFFFFu, a, o);
        if (lane == 0) {
            out[0] = -a;
            g_done = 0;          // reset for next graph replay
        }
    }
}

extern "C" void kernel_launch(void* const* d_in, const int* in_sizes, int n_in,
                              void* d_out, int out_size)
{
    const float* x  = (const float*)d_in[0];
    const float* y  = (const float*)d_in[1];
    const int*   ci = (const int*)d_in[2];
    const int*   ri = (const int*)d_in[3];
    const int*   di = (const int*)d_in[4];
    const int*   wl = (const int*)d_in[5];

    streamA<<<GA, NT>>>((const float4*)x, (const float4*)y);
    phaseB<<<GB, NT>>>(x, y, ci, ri, di, wl, (float*)d_out);
}

// round 9
// speedup vs baseline: 1.3653x; 1.3653x over previous
#include <cuda_runtime.h>

#define BB 2048
#define CC 9605
#define NT 256
#define NW (NT / 32)
#define CAP 1024
#define XTHRESH 2.0f
#define EPSF 1e-8f
#define NEG_INF -3.402823e38f

__device__ float g_partials[BB];
__device__ int   g_done = 0;

// base * w for one element; y is exactly 0.0f or 1.0f so FFMA blends replace selects
__device__ __forceinline__ float term_bw(float xv, float yv) {
    float p  = __fdividef(1.0f, 1.0f + __expf(-xv));   // sigmoid
    float xn = fminf(1.05f - p, 1.0f);                 // xs_neg
    float o  = fmaxf(p - 0.05f, 0.0f);                 // 1 - xs_neg
    float o2 = o * o;
    float o4 = o2 * o2;                                // (1-pt)^4 (neg)
    float arg = fmaf(yv, fmaxf(p, EPSF) - xn, xn);     // pos ? max(p,eps) : xn
    float w   = fmaf(yv, (1.0f - p) - o4, o4);         // pos ? (1-p) : o4
    return __logf(arg) * w;
}

// monotone float->uint mapping so u64 key max == (max val, then min idx)
__device__ __forceinline__ unsigned long long pack_key(float v, int idx) {
    unsigned u = __float_as_uint(v);
    u = (u & 0x80000000u) ? ~u : (u | 0x80000000u);
    return ((unsigned long long)u << 32) | (unsigned)(0xFFFFFFFFu - (unsigned)idx);
}

__global__ __launch_bounds__(NT)
void loss_kernel(const float* __restrict__ x, const float* __restrict__ y,
                 const int* __restrict__ ci, const int* __restrict__ ri,
                 const int* __restrict__ di, const int* __restrict__ wl,
                 float* __restrict__ out)
{
    const int row = blockIdx.x;
    const float* __restrict__ xr = x + (size_t)row * CC;
    const float* __restrict__ yr = y + (size_t)row * CC;

    // alignment prologue: row*CC % 4 == row % 4 -> peel p head elements
    const int p  = (4 - (row & 3)) & 3;
    const int nb = (CC - p) >> 2;
    const int tail_start = p + 4 * nb;

    const float4* __restrict__ x4 = (const float4*)(xr + p);
    const float4* __restrict__ y4 = (const float4*)(yr + p);

    __shared__ float s_cval[CAP];
    __shared__ int   s_cidx[CAP];
    __shared__ int   s_count;
    __shared__ int   s_flags;
    __shared__ float s_wsum[NW];
    __shared__ int   s_sel[10];

    const int tid  = threadIdx.x;
    const int lane = tid & 31;
    const int wid  = tid >> 5;

    if (tid == 0) { s_count = 0; s_flags = 0; }
    __syncthreads();

    // per-sample ground-truth whitelist group flags (170 sparse y lookups)
    if (tid < 30) {
        if (yr[ci[tid]] > 0.5f) atomicOr(&s_flags, 1);
    } else if (tid < 100) {
        if (yr[ri[tid - 30]] > 0.5f) atomicOr(&s_flags, 2);
    } else if (tid < 170) {
        if (yr[di[tid - 100]] > 0.5f) atomicOr(&s_flags, 4);
    }

    // main streaming pass: distance-2 software pipeline (4 LDG.128 in flight)
    float acc = 0.0f;
    int i = tid;
    bool h0 = i < nb;
    bool h1 = i + NT < nb;
    float4 xa, ya, xb, yb;
    if (h0) { xa = __ldcs(x4 + i);      ya = __ldcs(y4 + i); }
    if (h1) { xb = __ldcs(x4 + i + NT); yb = __ldcs(y4 + i + NT); }
    while (h0) {
        int i2 = i + 2 * NT;
        bool h2 = i2 < nb;
        float4 xc, yc;
        if (h2) { xc = __ldcs(x4 + i2); yc = __ldcs(y4 + i2); }

        acc += term_bw(xa.x, ya.x) + term_bw(xa.y, ya.y)
             + term_bw(xa.z, ya.z) + term_bw(xa.w, ya.w);

        float mx = fmaxf(fmaxf(xa.x, xa.y), fmaxf(xa.z, xa.w));
        if (mx > XTHRESH) {                         // rare (~9% of float4s)
            int nl = (xa.x > XTHRESH) + (xa.y > XTHRESH)
                   + (xa.z > XTHRESH) + (xa.w > XTHRESH);
            int k = atomicAdd(&s_count, nl);
            int c0 = p + 4 * i;
            if (xa.x > XTHRESH) { if (k < CAP) { s_cval[k] = xa.x; s_cidx[k] = c0;     } k++; }
            if (xa.y > XTHRESH) { if (k < CAP) { s_cval[k] = xa.y; s_cidx[k] = c0 + 1; } k++; }
            if (xa.z > XTHRESH) { if (k < CAP) { s_cval[k] = xa.z; s_cidx[k] = c0 + 2; } k++; }
            if (xa.w > XTHRESH) { if (k < CAP) { s_cval[k] = xa.w; s_cidx[k] = c0 + 3; } }
        }

        xa = xb; ya = yb; h0 = h1;
        xb = xc; yb = yc; h1 = h2;
        i += NT;
    }

    // head (p elems) + tail (<=3 elems): thread 0
    if (tid == 0) {
        for (int c = 0; c < p; c++) {
            float xv = xr[c], yv = yr[c];
            acc += term_bw(xv, yv);
            if (xv > XTHRESH) {
                int k = atomicAdd(&s_count, 1);
                if (k < CAP) { s_cval[k] = xv; s_cidx[k] = c; }
            }
        }
        for (int c = tail_start; c < CC; c++) {
            float xv = xr[c], yv = yr[c];
            acc += term_bw(xv, yv);
            if (xv > XTHRESH) {
                int k = atomicAdd(&s_count, 1);
                if (k < CAP) { s_cval[k] = xv; s_cidx[k] = c; }
            }
        }
    }

    // warp partial sums
    #pragma unroll
    for (int o = 16; o > 0; o >>= 1) acc += __shfl_xor_sync(0xFFFFFFFFu, acc, o);
    if (lane == 0) s_wsum[wid] = acc;

    __syncthreads();          // candidates + flags + wsums visible
    if (wid != 0) return;     // warps 1..7 done; warp 0 finishes the row

    const int  cnt = s_count;
    const bool fb  = (cnt < 10) || (cnt > CAP);   // guaranteed-correct slow path

    if (!fb) {
        // 10 argmax passes over ~cnt candidates, u64 keys, warp-only
        for (int r = 0; r < 10; r++) {
            unsigned long long best = 0ull;
            for (int k = lane; k < cnt; k += 32) {
                unsigned long long key = pack_key(s_cval[k], s_cidx[k]);
                if (key > best) best = key;
            }
            #pragma unroll
            for (int o = 16; o > 0; o >>= 1) {
                unsigned long long t = __shfl_xor_sync(0xFFFFFFFFu, best, o);
                if (t > best) best = t;
            }
            int idx = (int)(0xFFFFFFFFu - (unsigned)best);
            if (lane == 0) s_sel[r] = idx;
            for (int k = lane; k < cnt; k += 32)
                if (s_cidx[k] == idx) s_cval[k] = NEG_INF;
            __syncwarp();
        }
    } else {
        // fallback: 10 argmax passes over the full row (never on this data)
        for (int r = 0; r < 10; r++) {
            unsigned long long best = 0ull;
            for (int c = lane; c < CC; c += 32) {
                bool used = false;
                for (int q = 0; q < r; q++) used |= (s_sel[q] == c);
                if (!used) {
                    unsigned long long key = pack_key(xr[c], c);
                    if (key > best) best = key;
                }
            }
            #pragma unroll
            for (int o = 16; o > 0; o >>= 1) {
                unsigned long long t = __shfl_xor_sync(0xFFFFFFFFu, best, o);
                if (t > best) best = t;
            }
            if (lane == 0) s_sel[r] = (int)(0xFFFFFFFFu - (unsigned)best);
            __syncwarp();
        }
    }

    // block sum (8 warp partials) via warp 0
    float bsum = (lane < NW) ? s_wsum[lane] : 0.0f;
    #pragma unroll
    for (int o = 16; o > 0; o >>= 1) bsum += __shfl_xor_sync(0xFFFFFFFFu, bsum, o);

    if (lane == 0) {
        // sequential 10-rank whitelist scan + correction
        int fl = s_flags;
        bool h1f = fl & 1, h2f = fl & 2, h3f = fl & 4;
        bool only4 = !(h1f || h2f || h3f);
        bool found = false;
        float fm[10];
        #pragma unroll
        for (int r = 0; r < 10; r++) {
            int j = s_sel[r];
            int wv = wl[j];
            bool in_map = wv > 0;
            bool in_gt = (wv == 1 && h1f) || (wv == 2 && h2f) ||
                         (wv == 3 && h3f) || (wv == 4 && only4);
            float f = 1.0f;
            if (in_map && only4) f *= 0.5f;                  // ALPHA_OTHER
            if (in_map && !in_gt && !found) f *= 2.0f;       // ALPHA1
            fm[r] = f;
            found = found || (in_map && in_gt);
        }
        float extra = found ? 1.0f : 2.0f;                   // post-scan ALPHA1
        float corr = 0.0f;
        #pragma unroll
        for (int r = 0; r < 10; r++) {
            float m = fm[r] * extra;
            if (m != 1.0f) {
                int j = s_sel[r];
                corr += term_bw(xr[j], yr[j]) * (m - 1.0f);
            }
        }
        g_partials[row] = bsum + corr;
    }

    // last block fuses the final reduction (fixed-order -> deterministic)
    int done = 0;
    if (lane == 0) {
        __threadfence();
        done = atomicAdd(&g_done, 1);
    }
    done = __shfl_sync(0xFFFFFFFFu, done, 0);
    if (done == BB - 1) {
        __threadfence();
        float a = 0.0f;
        for (int k = lane; k < BB; k += 32) a += g_partials[k];
        #pragma unroll
        for (int o = 16; o > 0; o >>= 1) a += __shfl_xor_sync(0xFFFFFFFFu, a, o);
        if (lane == 0) {
            out[0] = -a;
            g_done = 0;        // reset for next graph replay
        }
    }
}

extern "C" void kernel_launch(void* const* d_in, const int* in_sizes, int n_in,
                              void* d_out, int out_size)
{
    const float* x  = (const float*)d_in[0];
    const float* y  = (const float*)d_in[1];
    const int*   ci = (const int*)d_in[2];
    const int*   ri = (const int*)d_in[3];
    const int*   di = (const int*)d_in[4];
    const int*   wl = (const int*)d_in[5];

    loss_kernel<<<BB, NT>>>(x, y, ci, ri, di, wl, (float*)d_out);
}

// round 11
// speedup vs baseline: 1.6496x; 1.2083x over previous
#include <cuda_runtime.h>

#define BB 2048
#define CC 9605
#define NT 256
#define NW (NT / 32)
#define NFULL 9            // nb >= 2400 = 9*256 + 96, so iterations 0..8 always in bounds
#define CAP 1024
#define XTHRESH 2.4f
#define EPSF 1e-8f
#define LN2F 0.69314718055994531f
#define NEG_INF -3.402823e38f

__device__ float g_partials[BB];
__device__ int   g_done = 0;

// (base * w) in log2 units; y is exactly 0.0f or 1.0f so FFMA blends replace selects
__device__ __forceinline__ float term_bw2(float xv, float yv) {
    float p  = __fdividef(1.0f, 1.0f + __expf(-xv));   // sigmoid
    float xn = fminf(1.05f - p, 1.0f);                 // xs_neg
    float o  = fmaxf(p - 0.05f, 0.0f);                 // 1 - xs_neg
    float o2 = o * o;
    float o4 = o2 * o2;                                // (1-pt)^4 (neg)
    float arg = fmaf(yv, fmaxf(p, EPSF) - xn, xn);     // pos ? max(p,eps) : xn
    float w   = fmaf(yv, (1.0f - p) - o4, o4);         // pos ? (1-p) : o4
    return __log2f(arg) * w;                           // *ln2 folded at row level
}

__device__ __forceinline__ float term4(const float4& xv, const float4& yv) {
    return term_bw2(xv.x, yv.x) + term_bw2(xv.y, yv.y)
         + term_bw2(xv.z, yv.z) + term_bw2(xv.w, yv.w);
}

// monotone float->uint mapping so u64 key max == (max val, then min idx)
__device__ __forceinline__ unsigned long long pack_key(float v, int idx) {
    unsigned u = __float_as_uint(v);
    u = (u & 0x80000000u) ? ~u : (u | 0x80000000u);
    return ((unsigned long long)u << 32) | (unsigned)(0xFFFFFFFFu - (unsigned)idx);
}

__global__ __launch_bounds__(NT)
void loss_kernel(const float* __restrict__ x, const float* __restrict__ y,
                 const int* __restrict__ ci, const int* __restrict__ ri,
                 const int* __restrict__ di, const int* __restrict__ wl,
                 float* __restrict__ out)
{
    const int row = blockIdx.x;
    const float* __restrict__ xr = x + (size_t)row * CC;
    const float* __restrict__ yr = y + (size_t)row * CC;

    // alignment prologue: row*CC % 4 == row % 4 -> peel p head elements
    const int p  = (4 - (row & 3)) & 3;
    const int nb = (CC - p) >> 2;                 // 2400 or 2401
    const int tail_start = p + 4 * nb;

    const float4* __restrict__ x4 = (const float4*)(xr + p);
    const float4* __restrict__ y4 = (const float4*)(yr + p);

    __shared__ float s_cval[CAP];
    __shared__ int   s_cidx[CAP];
    __shared__ int   s_count;
    __shared__ int   s_flags;
    __shared__ float s_wsum[NW];
    __shared__ int   s_sel[10];

    const int tid  = threadIdx.x;
    const int lane = tid & 31;
    const int wid  = tid >> 5;

    if (tid == 0) { s_count = 0; s_flags = 0; }
    __syncthreads();

    // per-sample ground-truth whitelist group flags (170 sparse y lookups)
    if (tid < 30) {
        if (yr[ci[tid]] > 0.5f) atomicOr(&s_flags, 1);
    } else if (tid < 100) {
        if (yr[ri[tid - 30]] > 0.5f) atomicOr(&s_flags, 2);
    } else if (tid < 170) {
        if (yr[di[tid - 100]] > 0.5f) atomicOr(&s_flags, 4);
    }

    // ── branchless hot loop: pure math + 1-bit candidate flag per iteration ──
    float acc = 0.0f;
    unsigned cmask = 0;
    #pragma unroll
    for (int it = 0; it < NFULL; it++) {          // always in bounds
        int i = tid + it * NT;
        float4 xv = __ldcs(x4 + i);
        float4 yv = __ldcs(y4 + i);
        acc += term4(xv, yv);
        float mx = fmaxf(fmaxf(xv.x, xv.y), fmaxf(xv.z, xv.w));
        cmask |= (mx > XTHRESH) ? (1u << it) : 0u;
    }
    {   // guarded final iteration
        int i = tid + NFULL * NT;
        if (i < nb) {
            float4 xv = __ldcs(x4 + i);
            float4 yv = __ldcs(y4 + i);
            acc += term4(xv, yv);
            float mx = fmaxf(fmaxf(xv.x, xv.y), fmaxf(xv.z, xv.w));
            cmask |= (mx > XTHRESH) ? (1u << NFULL) : 0u;
        }
    }

    // deferred candidate pushes: revisit only flagged iterations (avg < 0.1/thread)
    while (cmask) {
        int it = __ffs(cmask) - 1;
        cmask &= cmask - 1;
        int i = tid + it * NT;
        float4 xv = __ldg(x4 + i);                // L2-resident reload
        int nl = (xv.x > XTHRESH) + (xv.y > XTHRESH)
               + (xv.z > XTHRESH) + (xv.w > XTHRESH);
        int k = atomicAdd(&s_count, nl);
        int c0 = p + 4 * i;
        if (xv.x > XTHRESH) { if (k < CAP) { s_cval[k] = xv.x; s_cidx[k] = c0;     } k++; }
        if (xv.y > XTHRESH) { if (k < CAP) { s_cval[k] = xv.y; s_cidx[k] = c0 + 1; } k++; }
        if (xv.z > XTHRESH) { if (k < CAP) { s_cval[k] = xv.z; s_cidx[k] = c0 + 2; } k++; }
        if (xv.w > XTHRESH) { if (k < CAP) { s_cval[k] = xv.w; s_cidx[k] = c0 + 3; } }
    }

    // head (p elems) + tail (<=3 elems): thread 0
    if (tid == 0) {
        for (int c = 0; c < p; c++) {
            float xv = xr[c], yv = yr[c];
            acc += term_bw2(xv, yv);
            if (xv > XTHRESH) {
                int k = atomicAdd(&s_count, 1);
                if (k < CAP) { s_cval[k] = xv; s_cidx[k] = c; }
            }
        }
        for (int c = tail_start; c < CC; c++) {
            float xv = xr[c], yv = yr[c];
            acc += term_bw2(xv, yv);
            if (xv > XTHRESH) {
                int k = atomicAdd(&s_count, 1);
                if (k < CAP) { s_cval[k] = xv; s_cidx[k] = c; }
            }
        }
    }

    // warp partial sums
    #pragma unroll
    for (int o = 16; o > 0; o >>= 1) acc += __shfl_xor_sync(0xFFFFFFFFu, acc, o);
    if (lane == 0) s_wsum[wid] = acc;

    __syncthreads();          // candidates + flags + wsums visible
    if (wid != 0) return;     // warps 1..7 done; warp 0 finishes the row

    const int  cnt = s_count;
    const bool fb  = (cnt < 10) || (cnt > CAP);   // guaranteed-correct slow path

    if (!fb) {
        // 10 argmax passes over ~cnt candidates, u64 keys, warp-only
        for (int r = 0; r < 10; r++) {
            unsigned long long best = 0ull;
            for (int k = lane; k < cnt; k += 32) {
                unsigned long long key = pack_key(s_cval[k], s_cidx[k]);
                if (key > best) best = key;
            }
            #pragma unroll
            for (int o = 16; o > 0; o >>= 1) {
                unsigned long long t = __shfl_xor_sync(0xFFFFFFFFu, best, o);
                if (t > best) best = t;
            }
            int idx = (int)(0xFFFFFFFFu - (unsigned)best);
            if (lane == 0) s_sel[r] = idx;
            for (int k = lane; k < cnt; k += 32)
                if (s_cidx[k] == idx) s_cval[k] = NEG_INF;
            __syncwarp();
        }
    } else {
        // fallback: 10 argmax passes over the full row (never on this data)
        for (int r = 0; r < 10; r++) {
            unsigned long long best = 0ull;
            for (int c = lane; c < CC; c += 32) {
                bool used = false;
                for (int q = 0; q < r; q++) used |= (s_sel[q] == c);
                if (!used) {
                    unsigned long long key = pack_key(xr[c], c);
                    if (key > best) best = key;
                }
            }
            #pragma unroll
            for (int o = 16; o > 0; o >>= 1) {
                unsigned long long t = __shfl_xor_sync(0xFFFFFFFFu, best, o);
                if (t > best) best = t;
            }
            if (lane == 0) s_sel[r] = (int)(0xFFFFFFFFu - (unsigned)best);
            __syncwarp();
        }
    }

    // block sum (8 warp partials) via warp 0
    float bsum = (lane < NW) ? s_wsum[lane] : 0.0f;
    #pragma unroll
    for (int o = 16; o > 0; o >>= 1) bsum += __shfl_xor_sync(0xFFFFFFFFu, bsum, o);

    if (lane == 0) {
        // sequential 10-rank whitelist scan + correction
        int fl = s_flags;
        bool h1f = fl & 1, h2f = fl & 2, h3f = fl & 4;
        bool only4 = !(h1f || h2f || h3f);
        bool found = false;
        float fm[10];
        #pragma unroll
        for (int r = 0; r < 10; r++) {
            int j = s_sel[r];
            int wv = wl[j];
            bool in_map = wv > 0;
            bool in_gt = (wv == 1 && h1f) || (wv == 2 && h2f) ||
                         (wv == 3 && h3f) || (wv == 4 && only4);
            float f = 1.0f;
            if (in_map && only4) f *= 0.5f;                  // ALPHA_OTHER
            if (in_map && !in_gt && !found) f *= 2.0f;       // ALPHA1
            fm[r] = f;
            found = found || (in_map && in_gt);
        }
        float extra = found ? 1.0f : 2.0f;                   // post-scan ALPHA1
        float corr = 0.0f;
        #pragma unroll
        for (int r = 0; r < 10; r++) {
            float m = fm[r] * extra;
            if (m != 1.0f) {
                int j = s_sel[r];
                corr += term_bw2(xr[j], yr[j]) * (m - 1.0f);
            }
        }
        g_partials[row] = (bsum + corr) * LN2F;              // log2 -> ln
    }

    // last block fuses the final reduction (fixed-order -> deterministic)
    int done = 0;
    if (lane == 0) {
        __threadfence();
        done = atomicAdd(&g_done, 1);
    }
    done = __shfl_sync(0xFFFFFFFFu, done, 0);
    if (done == BB - 1) {
        __threadfence();
        float a = 0.0f;
        for (int k = lane; k < BB; k += 32) a += g_partials[k];
        #pragma unroll
        for (int o = 16; o > 0; o >>= 1) a += __shfl_xor_sync(0xFFFFFFFFu, a, o);
        if (lane == 0) {
            out[0] = -a;
            g_done = 0;        // reset for next graph replay
        }
    }
}

extern "C" void kernel_launch(void* const* d_in, const int* in_sizes, int n_in,
                              void* d_out, int out_size)
{
    const float* x  = (const float*)d_in[0];
    const float* y  = (const float*)d_in[1];
    const int*   ci = (const int*)d_in[2];
    const int*   ri = (const int*)d_in[3];
    const int*   di = (const int*)d_in[4];
    const int*   wl = (const int*)d_in[5];

    loss_kernel<<<BB, NT>>>(x, y, ci, ri, di, wl, (float*)d_out);
}